// round 10
// baseline (speedup 1.0000x reference)
#include <cuda_runtime.h>
#include <cuda_bf16.h>
#include <math.h>
#include <stdint.h>

// Problem constants
#define BB 32
#define TT 1024
#define HH 1024
#define LL 4

// Recurrence config: 128 CTAs x (8 cols, all 32 batches), 8-way k-split
#define NCTA 128
#define CPC  8
#define KPW  128
#define RNN_SMEM ((HH*CPC + HH*BB + 8*CPC*BB) * 4)

// GEMM smem strides (bank-conflict-free ldmatrix)
#define AS_STRIDE 24     // 16 k-cols padded to 24 bf16 (48B rows)
#define WS_STRIDE 136    // 128 n-cols padded to 136 bf16 (272B rows)

// -------------------- device scratch --------------------
// Sequence buffers are T-MAJOR: row index m = t*BB + b, i.e. S[(t*BB+b)*HH + h].
__device__ float          g_S [BB * TT * HH];    // 128 MB fp32 sequence buffer
__device__ __nv_bfloat16  g_Ah[BB * TT * HH];    // 64 MB  input hi
__device__ __nv_bfloat16  g_Al[BB * TT * HH];    // 64 MB  input lo
__device__ __nv_bfloat16  g_Wih[LL * HH * HH];   // 8 MB   Wi hi
__device__ __nv_bfloat16  g_Wil[LL * HH * HH];   // 8 MB   Wi lo
__device__ float g_hA[HH * BB];                  // h ping (k-major [k][b])
__device__ float g_hB[HH * BB];                  // h pong
__device__ unsigned g_bar;                       // grid barrier counter

// -------------------- helpers --------------------
__device__ __forceinline__ float tanh_acc(float x)
{
    float ax = fabsf(x);
    float e  = __expf(-2.0f * ax);
    float r  = (1.0f - e) / (1.0f + e);
    return copysignf(r, x);
}
__device__ __forceinline__ uint32_t smem_u32(const void* p)
{
    uint32_t a;
    asm("{ .reg .u64 t; cvta.to.shared.u64 t, %1; cvt.u32.u64 %0, t; }" : "=r"(a) : "l"(p));
    return a;
}
__device__ __forceinline__ void cp_async16(uint32_t dst, const void* src)
{
    asm volatile("cp.async.cg.shared.global [%0], [%1], 16;" :: "r"(dst), "l"(src));
}
#define CP_COMMIT() asm volatile("cp.async.commit_group;")
#define CP_WAIT(N)  asm volatile("cp.async.wait_group " #N ";" ::: "memory")

__device__ __forceinline__ void red_release_add(unsigned* p, unsigned v)
{
    asm volatile("red.release.gpu.global.add.u32 [%0], %1;" :: "l"(p), "r"(v) : "memory");
}
__device__ __forceinline__ unsigned ld_acquire(unsigned* p)
{
    unsigned v;
    asm volatile("ld.acquire.gpu.global.u32 %0, [%1];" : "=r"(v) : "l"(p) : "memory");
    return v;
}
__device__ __forceinline__ void ldsm_x4(uint32_t& r0, uint32_t& r1, uint32_t& r2, uint32_t& r3,
                                        uint32_t a)
{
    asm volatile("ldmatrix.sync.aligned.m8n8.x4.shared.b16 {%0,%1,%2,%3}, [%4];"
                 : "=r"(r0), "=r"(r1), "=r"(r2), "=r"(r3) : "r"(a));
}
__device__ __forceinline__ void ldsm_x4_t(uint32_t& r0, uint32_t& r1, uint32_t& r2, uint32_t& r3,
                                          uint32_t a)
{
    asm volatile("ldmatrix.sync.aligned.m8n8.x4.trans.shared.b16 {%0,%1,%2,%3}, [%4];"
                 : "=r"(r0), "=r"(r1), "=r"(r2), "=r"(r3) : "r"(a));
}
__device__ __forceinline__ void mma16816(float* d, uint32_t a0, uint32_t a1, uint32_t a2,
                                         uint32_t a3, uint32_t b0, uint32_t b1)
{
    asm volatile(
        "mma.sync.aligned.m16n8k16.row.col.f32.bf16.bf16.f32 "
        "{%0,%1,%2,%3}, {%4,%5,%6,%7}, {%8,%9}, {%0,%1,%2,%3};"
        : "+f"(d[0]), "+f"(d[1]), "+f"(d[2]), "+f"(d[3])
        : "r"(a0), "r"(a1), "r"(a2), "r"(a3), "r"(b0), "r"(b1));
}

__device__ __forceinline__ void split_store(float v, __nv_bfloat16* hi, __nv_bfloat16* lo)
{
    __nv_bfloat16 h = __float2bfloat16(v);
    *hi = h;
    *lo = __float2bfloat16(v - __bfloat162float(h));
}

// -------------------- split fp32 -> bf16 hi/lo (elementwise, layout-preserving) ------
__global__ void __launch_bounds__(256)
split_kernel(const float* __restrict__ src, __nv_bfloat16* __restrict__ hi,
             __nv_bfloat16* __restrict__ lo, int n4)
{
    int i = blockIdx.x * blockDim.x + threadIdx.x;
    const int stride = gridDim.x * blockDim.x;
    const float4* s4 = (const float4*)src;
    __nv_bfloat162* h2 = (__nv_bfloat162*)hi;
    __nv_bfloat162* l2 = (__nv_bfloat162*)lo;
    for (; i < n4; i += stride) {
        float4 v = s4[i];
        __nv_bfloat16 hx = __float2bfloat16(v.x), hy = __float2bfloat16(v.y);
        __nv_bfloat16 hz = __float2bfloat16(v.z), hw = __float2bfloat16(v.w);
        __nv_bfloat16 lx = __float2bfloat16(v.x - __bfloat162float(hx));
        __nv_bfloat16 ly = __float2bfloat16(v.y - __bfloat162float(hy));
        __nv_bfloat16 lz = __float2bfloat16(v.z - __bfloat162float(hz));
        __nv_bfloat16 lw = __float2bfloat16(v.w - __bfloat162float(hw));
        __nv_bfloat162 a; a.x = hx; a.y = hy;
        __nv_bfloat162 b; b.x = hz; b.y = hw;
        __nv_bfloat162 c; c.x = lx; c.y = ly;
        __nv_bfloat162 d; d.x = lz; d.y = lw;
        h2[2 * i] = a; h2[2 * i + 1] = b;
        l2[2 * i] = c; l2[2 * i + 1] = d;
    }
}

// -------------------- split + transpose: x [b][t][h] fp32 -> Ah/Al t-major rows ------
__global__ void __launch_bounds__(256)
split_tr_kernel(const float* __restrict__ src, __nv_bfloat16* __restrict__ hi,
                __nv_bfloat16* __restrict__ lo)
{
    const int r = blockIdx.x;            // read row r = b*TT + t (contiguous read)
    const int b = r >> 10;
    const int t = r & (TT - 1);
    const int dr = t * BB + b;           // t-major destination row

    const float4* s = (const float4*)(src + (size_t)r * HH) + threadIdx.x;
    __nv_bfloat162* h2 = (__nv_bfloat162*)(hi + (size_t)dr * HH) + threadIdx.x * 2;
    __nv_bfloat162* l2 = (__nv_bfloat162*)(lo + (size_t)dr * HH) + threadIdx.x * 2;

    float4 v = *s;
    __nv_bfloat16 hx = __float2bfloat16(v.x), hy = __float2bfloat16(v.y);
    __nv_bfloat16 hz = __float2bfloat16(v.z), hw = __float2bfloat16(v.w);
    __nv_bfloat162 a; a.x = hx; a.y = hy;
    __nv_bfloat162 bb; bb.x = hz; bb.y = hw;
    __nv_bfloat162 c; c.x = __float2bfloat16(v.x - __bfloat162float(hx));
                      c.y = __float2bfloat16(v.y - __bfloat162float(hy));
    __nv_bfloat162 d; d.x = __float2bfloat16(v.z - __bfloat162float(hz));
                      d.y = __float2bfloat16(v.w - __bfloat162float(hw));
    h2[0] = a; h2[1] = bb;
    l2[0] = c; l2[1] = d;
}

// -------------------- tensor-core GEMM: C = (Ah+Al)@(Wh+Wl) + bias --------------------
// Row-wise over m: works identically for any row ordering (we use t-major rows).
__global__ void __launch_bounds__(256, 2)
mma_gemm_kernel(const __nv_bfloat16* __restrict__ Ahg0, const __nv_bfloat16* __restrict__ Alg0,
                const __nv_bfloat16* __restrict__ Whg0, const __nv_bfloat16* __restrict__ Wlg0,
                const float* __restrict__ bias, float* __restrict__ C)
{
    if (blockIdx.x == 0 && blockIdx.y == 0 && threadIdx.x == 0) g_bar = 0u;

    __shared__ __nv_bfloat16 Ah_s[2][128 * AS_STRIDE];
    __shared__ __nv_bfloat16 Al_s[2][128 * AS_STRIDE];
    __shared__ __nv_bfloat16 Wh_s[2][16 * WS_STRIDE];
    __shared__ __nv_bfloat16 Wl_s[2][16 * WS_STRIDE];

    const int tid  = threadIdx.x;
    const int bn   = blockIdx.x;
    const int bm   = blockIdx.y;
    const int wid  = tid >> 5;
    const int lane = tid & 31;
    const int wr   = wid & 3;
    const int wc   = wid >> 2;

    const int arow  = tid >> 1, ahalf = (tid & 1) * 8;
    const int wrow  = tid >> 4, wseg  = (tid & 15) * 8;

    const __nv_bfloat16* Ahg = Ahg0 + (size_t)(bm * 128 + arow) * HH + ahalf;
    const __nv_bfloat16* Alg = Alg0 + (size_t)(bm * 128 + arow) * HH + ahalf;
    const __nv_bfloat16* Whg = Whg0 + (size_t)wrow * HH + bn * 128 + wseg;
    const __nv_bfloat16* Wlg = Wlg0 + (size_t)wrow * HH + bn * 128 + wseg;

    const uint32_t bAh = smem_u32(Ah_s), bAl = smem_u32(Al_s);
    const uint32_t bWh = smem_u32(Wh_s), bWl = smem_u32(Wl_s);
    const uint32_t dA = (arow * AS_STRIDE + ahalf) * 2;
    const uint32_t dW = (wrow * WS_STRIDE + wseg) * 2;
    const uint32_t ASZ = 128 * AS_STRIDE * 2;
    const uint32_t WSZ = 16 * WS_STRIDE * 2;

    const uint32_t aOff = (((wr * 32) + (lane & 15)) * AS_STRIDE + ((lane >> 4) << 3)) * 2;
    const uint32_t bOff = ((lane & 15) * WS_STRIDE + wc * 64 + ((lane >> 4) << 3)) * 2;

    float acc[2][8][4];
#pragma unroll
    for (int mi = 0; mi < 2; mi++)
#pragma unroll
        for (int ni = 0; ni < 8; ni++)
#pragma unroll
            for (int q = 0; q < 4; q++) acc[mi][ni][q] = 0.0f;

    cp_async16(bAh + dA, Ahg);
    cp_async16(bAl + dA, Alg);
    cp_async16(bWh + dW, Whg);
    cp_async16(bWl + dW, Wlg);
    CP_COMMIT();

    for (int ks = 0; ks < 64; ks++) {
        const uint32_t cur = (ks & 1);
        if (ks < 63) {
            const uint32_t nxt = cur ^ 1;
            const int kb = (ks + 1) * 16;
            cp_async16(bAh + nxt * ASZ + dA, Ahg + kb);
            cp_async16(bAl + nxt * ASZ + dA, Alg + kb);
            cp_async16(bWh + nxt * WSZ + dW, Whg + (size_t)kb * HH);
            cp_async16(bWl + nxt * WSZ + dW, Wlg + (size_t)kb * HH);
            CP_COMMIT();
            CP_WAIT(1);
        } else {
            CP_WAIT(0);
        }
        __syncthreads();

        uint32_t ah[2][4], al[2][4];
#pragma unroll
        for (int mi = 0; mi < 2; mi++) {
            const uint32_t mofs = mi * 16 * AS_STRIDE * 2;
            ldsm_x4(ah[mi][0], ah[mi][1], ah[mi][2], ah[mi][3], bAh + cur * ASZ + aOff + mofs);
            ldsm_x4(al[mi][0], al[mi][1], al[mi][2], al[mi][3], bAl + cur * ASZ + aOff + mofs);
        }
#pragma unroll
        for (int ng = 0; ng < 4; ng++) {
            uint32_t bh[4], blr[4];
            ldsm_x4_t(bh[0], bh[1], bh[2], bh[3], bWh + cur * WSZ + bOff + ng * 32);
            ldsm_x4_t(blr[0], blr[1], blr[2], blr[3], bWl + cur * WSZ + bOff + ng * 32);
#pragma unroll
            for (int mi = 0; mi < 2; mi++) {
                mma16816(acc[mi][2 * ng],     ah[mi][0], ah[mi][1], ah[mi][2], ah[mi][3], bh[0], bh[1]);
                mma16816(acc[mi][2 * ng],     al[mi][0], al[mi][1], al[mi][2], al[mi][3], bh[0], bh[1]);
                mma16816(acc[mi][2 * ng],     ah[mi][0], ah[mi][1], ah[mi][2], ah[mi][3], blr[0], blr[1]);
                mma16816(acc[mi][2 * ng + 1], ah[mi][0], ah[mi][1], ah[mi][2], ah[mi][3], bh[2], bh[3]);
                mma16816(acc[mi][2 * ng + 1], al[mi][0], al[mi][1], al[mi][2], al[mi][3], bh[2], bh[3]);
                mma16816(acc[mi][2 * ng + 1], ah[mi][0], ah[mi][1], ah[mi][2], ah[mi][3], blr[2], blr[3]);
            }
        }
        __syncthreads();
    }

    const int gr  = lane >> 2;
    const int gc2 = (lane & 3) * 2;
#pragma unroll
    for (int mi = 0; mi < 2; mi++) {
        const int row0 = bm * 128 + wr * 32 + mi * 16 + gr;
#pragma unroll
        for (int ni = 0; ni < 8; ni++) {
            const int col = bn * 128 + wc * 64 + ni * 8 + gc2;
            const float b0 = bias[col], b1 = bias[col + 1];
            float2 v0 = { acc[mi][ni][0] + b0, acc[mi][ni][1] + b1 };
            float2 v1 = { acc[mi][ni][2] + b0, acc[mi][ni][3] + b1 };
            *(float2*)(C + (size_t)row0 * HH + col)        = v0;
            *(float2*)(C + (size_t)(row0 + 8) * HH + col)  = v1;
        }
    }
}

// -------------------- grid barrier --------------------
__device__ __forceinline__ void grid_bar_sync(unsigned target)
{
    __syncthreads();
    if (threadIdx.x == 0) {
        red_release_add(&g_bar, 1u);
        while (ld_acquire(&g_bar) < target) { }
    }
    __syncthreads();
}

// -------------------- Recurrence (fp32, 8-chunk pipelined h copy, t-major xp) --------
__global__ void __launch_bounds__(256, 1)
rnn_layer_kernel(float* __restrict__ xp, const float* __restrict__ Wh)
{
    extern __shared__ float sm[];
    float* w_s = sm;                         // [HH][CPC]
    float* h_s = sm + HH * CPC;              // [HH][BB]
    float* p_s = sm + HH * CPC + HH * BB;    // [8][CPC][BB]

    const int tid  = threadIdx.x;
    const int w    = tid >> 5;
    const int lane = tid & 31;
    const int c0   = blockIdx.x * CPC;

    for (int i = tid; i < HH * 2; i += 256) {
        int k = i >> 1, half = (i & 1) * 4;
        *(float4*)(w_s + k * CPC + half) = *(const float4*)(Wh + k * HH + c0 + half);
    }
    g_hA[blockIdx.x * 256 + tid] = 0.0f;

    unsigned bar = 1;
    grid_bar_sync(bar * NCTA); bar++;

    const int kbase = w * KPW;
    const uint32_t hsm = smem_u32(h_s) + kbase * BB * 4;
    const int oc = c0 + w;
    const int ob = lane;

    float* hcur = g_hA;
    float* hnxt = g_hB;

    const float*  hp = h_s + kbase * BB + lane;
    const float4* wp = (const float4*)(w_s + kbase * CPC);

    for (int t = 0; t < TT; t++) {
        // issue all 8 copy chunks first (2KB each; copies are the critical path)
        const float* src = hcur + kbase * BB;
#pragma unroll
        for (int g = 0; g < 8; g++) {
#pragma unroll
            for (int j = 0; j < 4; j++) {
                const int f4 = g * 128 + j * 32 + lane;
                cp_async16(hsm + f4 * 16, src + f4 * 4);
            }
            CP_COMMIT();
        }

        // t-major xp: contiguous 128KB slab per step
        const int xidx = (t * BB + ob) * HH + oc;
        const float xv = xp[xidx];

        float a0 = 0.f, a1 = 0.f, a2 = 0.f, a3 = 0.f;
        float a4 = 0.f, a5 = 0.f, a6 = 0.f, a7 = 0.f;

#define RNN_CHUNK(G)                                          \
        _Pragma("unroll")                                     \
        for (int k = (G)*16; k < (G)*16 + 16; k++) {          \
            float  hv = hp[k * BB];                           \
            float4 wa = wp[k * 2];                            \
            float4 wb = wp[k * 2 + 1];                        \
            a0 = fmaf(hv, wa.x, a0);                          \
            a1 = fmaf(hv, wa.y, a1);                          \
            a2 = fmaf(hv, wa.z, a2);                          \
            a3 = fmaf(hv, wa.w, a3);                          \
            a4 = fmaf(hv, wb.x, a4);                          \
            a5 = fmaf(hv, wb.y, a5);                          \
            a6 = fmaf(hv, wb.z, a6);                          \
            a7 = fmaf(hv, wb.w, a7);                          \
        }

        CP_WAIT(7); __syncwarp(); RNN_CHUNK(0);
        CP_WAIT(6); __syncwarp(); RNN_CHUNK(1);
        CP_WAIT(5); __syncwarp(); RNN_CHUNK(2);
        CP_WAIT(4); __syncwarp(); RNN_CHUNK(3);
        CP_WAIT(3); __syncwarp(); RNN_CHUNK(4);
        CP_WAIT(2); __syncwarp(); RNN_CHUNK(5);
        CP_WAIT(1); __syncwarp(); RNN_CHUNK(6);
        CP_WAIT(0); __syncwarp(); RNN_CHUNK(7);
#undef RNN_CHUNK

        float* pw = p_s + w * (CPC * BB) + lane;
        pw[0 * BB] = a0; pw[1 * BB] = a1; pw[2 * BB] = a2; pw[3 * BB] = a3;
        pw[4 * BB] = a4; pw[5 * BB] = a5; pw[6 * BB] = a6; pw[7 * BB] = a7;
        __syncthreads();

        const float* pr = p_s + w * BB + lane;
        float s = pr[0];
#pragma unroll
        for (int j = 1; j < 8; j++) s += pr[j * (CPC * BB)];

        const float hn = tanh_acc(xv + s);
        xp[xidx] = hn;
        hnxt[oc * BB + ob] = hn;

        grid_bar_sync(bar * NCTA); bar++;
        float* tmp = hcur; hcur = hnxt; hnxt = tmp;
    }
}

// -------------------- Final dense head (t-major: last slab is contiguous) ------------
__global__ void __launch_bounds__(256)
fc_kernel(const float* __restrict__ seq, const float* __restrict__ fcW,
          const float* __restrict__ fcb, float* __restrict__ out)
{
    const int o  = blockIdx.x * 256 + threadIdx.x;
    const int bq = blockIdx.y;
    const float* h = seq + (size_t)((TT - 1) * BB + bq) * HH;
    float acc = fcb[o];
#pragma unroll 8
    for (int k = 0; k < HH; k++)
        acc = fmaf(h[k], fcW[k * HH + o], acc);
    out[bq * HH + o] = acc;
}

// -------------------- launch --------------------
extern "C" void kernel_launch(void* const* d_in, const int* in_sizes, int n_in,
                              void* d_out, int out_size)
{
    const float* x   = (const float*)d_in[0];
    const float* Wi  = (const float*)d_in[1];
    const float* Wh  = (const float*)d_in[2];
    const float* bl  = (const float*)d_in[3];
    const float* fcW = (const float*)d_in[4];
    const float* fcb = (const float*)d_in[5];
    float* out = (float*)d_out;

    cudaFuncSetAttribute(rnn_layer_kernel,
                         cudaFuncAttributeMaxDynamicSharedMemorySize, RNN_SMEM);

    float *S;
    __nv_bfloat16 *Ah, *Al, *Wih, *Wil;
    cudaGetSymbolAddress((void**)&S,   g_S);
    cudaGetSymbolAddress((void**)&Ah,  g_Ah);
    cudaGetSymbolAddress((void**)&Al,  g_Al);
    cudaGetSymbolAddress((void**)&Wih, g_Wih);
    cudaGetSymbolAddress((void**)&Wil, g_Wil);

    const dim3 ggrid(8, 256);
    const int NSEQ4 = BB * TT * HH / 4;
    const int NW4   = LL * HH * HH / 4;

    // x: b-major fp32 -> t-major bf16 hi/lo; weights: elementwise split
    split_tr_kernel<<<BB * TT, 256>>>(x, Ah, Al);
    split_kernel<<<2048, 256>>>(Wi, Wih, Wil, NW4);

    for (int l = 0; l < LL; l++) {
        mma_gemm_kernel<<<ggrid, 256>>>(Ah, Al,
                                        Wih + (size_t)l * HH * HH,
                                        Wil + (size_t)l * HH * HH,
                                        bl + l * HH, S);
        rnn_layer_kernel<<<NCTA, 256, RNN_SMEM>>>(S, Wh + (size_t)l * HH * HH);
        if (l < LL - 1)
            split_kernel<<<4096, 256>>>(S, Ah, Al, NSEQ4);
    }

    fc_kernel<<<dim3(HH / 256, BB), 256>>>(S, fcW, fcb, out);
}

// round 14
// speedup vs baseline: 1.3878x; 1.3878x over previous
#include <cuda_runtime.h>
#include <cuda_bf16.h>
#include <math.h>
#include <stdint.h>

// Problem constants
#define BB 32
#define TT 1024
#define HH 1024
#define LL 4

// Recurrence config: 64 CTAs x (16 cols, all 32 batches), 8 warps k-split (128 k each)
#define NCTA_R 64
#define CPR    16
// SMEM: Wh hi/lo [1024k x 16c] 64KB + h hi/lo [32b x 1024k] 128KB + partials 16KB
#define RNN_SMEM_B (65536 + 131072 + 16384)   // 212992 B

// GEMM smem strides (bank-conflict-free ldmatrix)
#define AS_STRIDE 24
#define WS_STRIDE 136

// -------------------- device scratch --------------------
// Sequence buffers are T-MAJOR: row m = t*BB + b.
__device__ float          g_S [BB * TT * HH];    // 128 MB fp32 sequence buffer
__device__ __nv_bfloat16  g_Ah[BB * TT * HH];    // 64 MB  input hi
__device__ __nv_bfloat16  g_Al[BB * TT * HH];    // 64 MB  input lo
__device__ __nv_bfloat16  g_Wih[LL * HH * HH];   // Wi hi
__device__ __nv_bfloat16  g_Wil[LL * HH * HH];   // Wi lo
__device__ __nv_bfloat16  g_Whh[LL * HH * HH];   // Wh hi
__device__ __nv_bfloat16  g_Whl[LL * HH * HH];   // Wh lo
__device__ __nv_bfloat16  g_hhA[BB * HH], g_hlA[BB * HH];   // h hi/lo ping ([b][k])
__device__ __nv_bfloat16  g_hhB[BB * HH], g_hlB[BB * HH];   // h hi/lo pong
__device__ unsigned g_bar;

// -------------------- helpers --------------------
__device__ __forceinline__ float tanh_acc(float x)
{
    float ax = fabsf(x);
    float e  = __expf(-2.0f * ax);
    float r  = (1.0f - e) / (1.0f + e);
    return copysignf(r, x);
}
__device__ __forceinline__ uint32_t smem_u32(const void* p)
{
    uint32_t a;
    asm("{ .reg .u64 t; cvta.to.shared.u64 t, %1; cvt.u32.u64 %0, t; }" : "=r"(a) : "l"(p));
    return a;
}
__device__ __forceinline__ void cp_async16(uint32_t dst, const void* src)
{
    asm volatile("cp.async.cg.shared.global [%0], [%1], 16;" :: "r"(dst), "l"(src));
}
#define CP_COMMIT() asm volatile("cp.async.commit_group;")
#define CP_WAIT(N)  asm volatile("cp.async.wait_group " #N ";" ::: "memory")

__device__ __forceinline__ void red_release_add(unsigned* p, unsigned v)
{
    asm volatile("red.release.gpu.global.add.u32 [%0], %1;" :: "l"(p), "r"(v) : "memory");
}
__device__ __forceinline__ unsigned ld_acquire(unsigned* p)
{
    unsigned v;
    asm volatile("ld.acquire.gpu.global.u32 %0, [%1];" : "=r"(v) : "l"(p) : "memory");
    return v;
}
__device__ __forceinline__ void ldsm_x4(uint32_t& r0, uint32_t& r1, uint32_t& r2, uint32_t& r3,
                                        uint32_t a)
{
    asm volatile("ldmatrix.sync.aligned.m8n8.x4.shared.b16 {%0,%1,%2,%3}, [%4];"
                 : "=r"(r0), "=r"(r1), "=r"(r2), "=r"(r3) : "r"(a));
}
__device__ __forceinline__ void ldsm_x4_t(uint32_t& r0, uint32_t& r1, uint32_t& r2, uint32_t& r3,
                                          uint32_t a)
{
    asm volatile("ldmatrix.sync.aligned.m8n8.x4.trans.shared.b16 {%0,%1,%2,%3}, [%4];"
                 : "=r"(r0), "=r"(r1), "=r"(r2), "=r"(r3) : "r"(a));
}
__device__ __forceinline__ void mma16816(float* d, uint32_t a0, uint32_t a1, uint32_t a2,
                                         uint32_t a3, uint32_t b0, uint32_t b1)
{
    asm volatile(
        "mma.sync.aligned.m16n8k16.row.col.f32.bf16.bf16.f32 "
        "{%0,%1,%2,%3}, {%4,%5,%6,%7}, {%8,%9}, {%0,%1,%2,%3};"
        : "+f"(d[0]), "+f"(d[1]), "+f"(d[2]), "+f"(d[3])
        : "r"(a0), "r"(a1), "r"(a2), "r"(a3), "r"(b0), "r"(b1));
}

// -------------------- split fp32 -> bf16 hi/lo (elementwise) --------------------
__global__ void __launch_bounds__(256)
split_kernel(const float* __restrict__ src, __nv_bfloat16* __restrict__ hi,
             __nv_bfloat16* __restrict__ lo, int n4)
{
    int i = blockIdx.x * blockDim.x + threadIdx.x;
    const int stride = gridDim.x * blockDim.x;
    const float4* s4 = (const float4*)src;
    __nv_bfloat162* h2 = (__nv_bfloat162*)hi;
    __nv_bfloat162* l2 = (__nv_bfloat162*)lo;
    for (; i < n4; i += stride) {
        float4 v = s4[i];
        __nv_bfloat16 hx = __float2bfloat16(v.x), hy = __float2bfloat16(v.y);
        __nv_bfloat16 hz = __float2bfloat16(v.z), hw = __float2bfloat16(v.w);
        __nv_bfloat162 a; a.x = hx; a.y = hy;
        __nv_bfloat162 b; b.x = hz; b.y = hw;
        __nv_bfloat162 c; c.x = __float2bfloat16(v.x - __bfloat162float(hx));
                          c.y = __float2bfloat16(v.y - __bfloat162float(hy));
        __nv_bfloat162 d; d.x = __float2bfloat16(v.z - __bfloat162float(hz));
                          d.y = __float2bfloat16(v.w - __bfloat162float(hw));
        h2[2 * i] = a; h2[2 * i + 1] = b;
        l2[2 * i] = c; l2[2 * i + 1] = d;
    }
}

// -------------------- split + transpose: x [b][t][h] fp32 -> t-major bf16 hi/lo -----
__global__ void __launch_bounds__(256)
split_tr_kernel(const float* __restrict__ src, __nv_bfloat16* __restrict__ hi,
                __nv_bfloat16* __restrict__ lo)
{
    const int r = blockIdx.x;
    const int b = r >> 10;
    const int t = r & (TT - 1);
    const int dr = t * BB + b;

    const float4* s = (const float4*)(src + (size_t)r * HH) + threadIdx.x;
    __nv_bfloat162* h2 = (__nv_bfloat162*)(hi + (size_t)dr * HH) + threadIdx.x * 2;
    __nv_bfloat162* l2 = (__nv_bfloat162*)(lo + (size_t)dr * HH) + threadIdx.x * 2;

    float4 v = *s;
    __nv_bfloat16 hx = __float2bfloat16(v.x), hy = __float2bfloat16(v.y);
    __nv_bfloat16 hz = __float2bfloat16(v.z), hw = __float2bfloat16(v.w);
    __nv_bfloat162 a; a.x = hx; a.y = hy;
    __nv_bfloat162 bb; bb.x = hz; bb.y = hw;
    __nv_bfloat162 c; c.x = __float2bfloat16(v.x - __bfloat162float(hx));
                      c.y = __float2bfloat16(v.y - __bfloat162float(hy));
    __nv_bfloat162 d; d.x = __float2bfloat16(v.z - __bfloat162float(hz));
                      d.y = __float2bfloat16(v.w - __bfloat162float(hw));
    h2[0] = a; h2[1] = bb;
    l2[0] = c; l2[1] = d;
}

// -------------------- tensor-core GEMM: C = (Ah+Al)@(Wh+Wl) + bias --------------------
__global__ void __launch_bounds__(256, 2)
mma_gemm_kernel(const __nv_bfloat16* __restrict__ Ahg0, const __nv_bfloat16* __restrict__ Alg0,
                const __nv_bfloat16* __restrict__ Whg0, const __nv_bfloat16* __restrict__ Wlg0,
                const float* __restrict__ bias, float* __restrict__ C)
{
    if (blockIdx.x == 0 && blockIdx.y == 0 && threadIdx.x == 0) g_bar = 0u;

    __shared__ __nv_bfloat16 Ah_s[2][128 * AS_STRIDE];
    __shared__ __nv_bfloat16 Al_s[2][128 * AS_STRIDE];
    __shared__ __nv_bfloat16 Wh_s[2][16 * WS_STRIDE];
    __shared__ __nv_bfloat16 Wl_s[2][16 * WS_STRIDE];

    const int tid  = threadIdx.x;
    const int bn   = blockIdx.x;
    const int bm   = blockIdx.y;
    const int wid  = tid >> 5;
    const int lane = tid & 31;
    const int wr   = wid & 3;
    const int wc   = wid >> 2;

    const int arow  = tid >> 1, ahalf = (tid & 1) * 8;
    const int wrow  = tid >> 4, wseg  = (tid & 15) * 8;

    const __nv_bfloat16* Ahg = Ahg0 + (size_t)(bm * 128 + arow) * HH + ahalf;
    const __nv_bfloat16* Alg = Alg0 + (size_t)(bm * 128 + arow) * HH + ahalf;
    const __nv_bfloat16* Whg = Whg0 + (size_t)wrow * HH + bn * 128 + wseg;
    const __nv_bfloat16* Wlg = Wlg0 + (size_t)wrow * HH + bn * 128 + wseg;

    const uint32_t bAh = smem_u32(Ah_s), bAl = smem_u32(Al_s);
    const uint32_t bWh = smem_u32(Wh_s), bWl = smem_u32(Wl_s);
    const uint32_t dA = (arow * AS_STRIDE + ahalf) * 2;
    const uint32_t dW = (wrow * WS_STRIDE + wseg) * 2;
    const uint32_t ASZ = 128 * AS_STRIDE * 2;
    const uint32_t WSZ = 16 * WS_STRIDE * 2;

    const uint32_t aOff = (((wr * 32) + (lane & 15)) * AS_STRIDE + ((lane >> 4) << 3)) * 2;
    const uint32_t bOff = ((lane & 15) * WS_STRIDE + wc * 64 + ((lane >> 4) << 3)) * 2;

    float acc[2][8][4];
#pragma unroll
    for (int mi = 0; mi < 2; mi++)
#pragma unroll
        for (int ni = 0; ni < 8; ni++)
#pragma unroll
            for (int q = 0; q < 4; q++) acc[mi][ni][q] = 0.0f;

    cp_async16(bAh + dA, Ahg);
    cp_async16(bAl + dA, Alg);
    cp_async16(bWh + dW, Whg);
    cp_async16(bWl + dW, Wlg);
    CP_COMMIT();

    for (int ks = 0; ks < 64; ks++) {
        const uint32_t cur = (ks & 1);
        if (ks < 63) {
            const uint32_t nxt = cur ^ 1;
            const int kb = (ks + 1) * 16;
            cp_async16(bAh + nxt * ASZ + dA, Ahg + kb);
            cp_async16(bAl + nxt * ASZ + dA, Alg + kb);
            cp_async16(bWh + nxt * WSZ + dW, Whg + (size_t)kb * HH);
            cp_async16(bWl + nxt * WSZ + dW, Wlg + (size_t)kb * HH);
            CP_COMMIT();
            CP_WAIT(1);
        } else {
            CP_WAIT(0);
        }
        __syncthreads();

        uint32_t ah[2][4], al[2][4];
#pragma unroll
        for (int mi = 0; mi < 2; mi++) {
            const uint32_t mofs = mi * 16 * AS_STRIDE * 2;
            ldsm_x4(ah[mi][0], ah[mi][1], ah[mi][2], ah[mi][3], bAh + cur * ASZ + aOff + mofs);
            ldsm_x4(al[mi][0], al[mi][1], al[mi][2], al[mi][3], bAl + cur * ASZ + aOff + mofs);
        }
#pragma unroll
        for (int ng = 0; ng < 4; ng++) {
            uint32_t bh[4], blr[4];
            ldsm_x4_t(bh[0], bh[1], bh[2], bh[3], bWh + cur * WSZ + bOff + ng * 32);
            ldsm_x4_t(blr[0], blr[1], blr[2], blr[3], bWl + cur * WSZ + bOff + ng * 32);
#pragma unroll
            for (int mi = 0; mi < 2; mi++) {
                mma16816(acc[mi][2 * ng],     ah[mi][0], ah[mi][1], ah[mi][2], ah[mi][3], bh[0], bh[1]);
                mma16816(acc[mi][2 * ng],     al[mi][0], al[mi][1], al[mi][2], al[mi][3], bh[0], bh[1]);
                mma16816(acc[mi][2 * ng],     ah[mi][0], ah[mi][1], ah[mi][2], ah[mi][3], blr[0], blr[1]);
                mma16816(acc[mi][2 * ng + 1], ah[mi][0], ah[mi][1], ah[mi][2], ah[mi][3], bh[2], bh[3]);
                mma16816(acc[mi][2 * ng + 1], al[mi][0], al[mi][1], al[mi][2], al[mi][3], bh[2], bh[3]);
                mma16816(acc[mi][2 * ng + 1], ah[mi][0], ah[mi][1], ah[mi][2], ah[mi][3], blr[2], blr[3]);
            }
        }
        __syncthreads();
    }

    const int gr  = lane >> 2;
    const int gc2 = (lane & 3) * 2;
#pragma unroll
    for (int mi = 0; mi < 2; mi++) {
        const int row0 = bm * 128 + wr * 32 + mi * 16 + gr;
#pragma unroll
        for (int ni = 0; ni < 8; ni++) {
            const int col = bn * 128 + wc * 64 + ni * 8 + gc2;
            const float b0 = bias[col], b1 = bias[col + 1];
            float2 v0 = { acc[mi][ni][0] + b0, acc[mi][ni][1] + b1 };
            float2 v1 = { acc[mi][ni][2] + b0, acc[mi][ni][3] + b1 };
            *(float2*)(C + (size_t)row0 * HH + col)        = v0;
            *(float2*)(C + (size_t)(row0 + 8) * HH + col)  = v1;
        }
    }
}

// -------------------- grid barrier --------------------
__device__ __forceinline__ void grid_bar_sync(unsigned target)
{
    __syncthreads();
    if (threadIdx.x == 0) {
        red_release_add(&g_bar, 1u);
        while (ld_acquire(&g_bar) < target) { }
    }
    __syncthreads();
}

// -------------------- Recurrence on tensor cores (bf16-split h @ Wh) ------------------
// CTA c: cols [c*16, c*16+16), all 32 batches. Warp w: k in [w*128, w*128+128).
// SMEM: Wh hi/lo [1024k][16c] (k-parity chunk swizzle), h hi/lo [32b][1024k]
// (XOR chunk swizzle, conflict-free ldmatrix), partials [8w][32b][16c] fp32.
__global__ void __launch_bounds__(256, 1)
rnn_layer_mma_kernel(float* __restrict__ xp,
                     const __nv_bfloat16* __restrict__ Whh,
                     const __nv_bfloat16* __restrict__ Whl)
{
    extern __shared__ char smraw[];
    const uint32_t smb = smem_u32(smraw);
    const uint32_t whb = smb;                 // Wh hi [0,32768), lo [32768,65536)
    const uint32_t hbs = smb + 65536;         // h hi [.. +65536), lo next 65536
    float* p_s = (float*)(smraw + 196608);    // 16KB partials

    const int tid  = threadIdx.x;
    const int w    = tid >> 5;
    const int lane = tid & 31;
    const int c0   = blockIdx.x * CPR;

    // ---- load Wh slice hi/lo into swizzled SMEM (per layer) ----
    // chunk (k, ch): dst byte = k*32 + ((ch ^ ((k>>2)&1)) << 4)
    for (int i = tid; i < HH * 2; i += 256) {
        int k = i >> 1, ch = i & 1;
        uint32_t sw = ((uint32_t)(ch ^ ((k >> 2) & 1))) << 4;
        *(uint4*)(smraw + k * 32 + sw) =
            *(const uint4*)(Whh + (size_t)k * HH + c0 + ch * 8);
        *(uint4*)(smraw + 32768 + k * 32 + sw) =
            *(const uint4*)(Whl + (size_t)k * HH + c0 + ch * 8);
    }
    // ---- zero initial hidden state (64 CTA x 256 thr covers 16384 u32 per buffer) ----
    {
        int zi = blockIdx.x * 256 + tid;
        ((uint32_t*)g_hhA)[zi] = 0u;
        ((uint32_t*)g_hlA)[zi] = 0u;
    }

    unsigned bar = 1;
    grid_bar_sync(bar * NCTA_R); bar++;

    const int kbase = w * 128;            // this warp's k range
    const int kcb   = w * 16;             // chunk base (k/8)
    const int brow  = lane & 15;
    const int klane = lane >> 4;
    const uint32_t asw   = (uint32_t)(brow & 7);
    const uint32_t bswzB = ((uint32_t)(klane ^ ((brow >> 2) & 1))) << 4;

    // output mapping: 2 outputs per thread: b = tid>>3, c = (tid&7)*2 (+0,+1)
    const int ob  = tid >> 3;
    const int ocl = (tid & 7) * 2;
    const int oc  = c0 + ocl;

    const __nv_bfloat16 *hhc = g_hhA, *hlc = g_hlA;
    __nv_bfloat16 *hhn = g_hhB, *hln = g_hlB;

    for (int t = 0; t < TT; t++) {
        const size_t xidx = (size_t)(t * BB + ob) * HH + oc;
        const float2 xv = *(const float2*)(xp + xidx);

        // ---- issue h copies: 4 groups (hh b0-15, hl b0-15, hh b16-31, hl b16-31) ----
#pragma unroll
        for (int half = 0; half < 2; half++) {
            const int gb0 = half * 16;
#pragma unroll
            for (int lohi = 0; lohi < 2; lohi++) {
                const __nv_bfloat16* buf = lohi ? hlc : hhc;
                const uint32_t dbase = hbs + (lohi ? 65536u : 0u);
#pragma unroll
                for (int j = 0; j < 8; j++) {
                    int idx = j * 32 + lane;
                    int b  = gb0 + (idx >> 4);
                    int ck = idx & 15;
                    uint32_t dst = dbase + (uint32_t)(b * 2048)
                                 + ((((uint32_t)(kcb + ck)) ^ ((uint32_t)(b & 7))) << 4);
                    cp_async16(dst, buf + (size_t)b * HH + kbase + ck * 8);
                }
                CP_COMMIT();
            }
        }

        float acc[2][2][4];
#pragma unroll
        for (int mi = 0; mi < 2; mi++)
#pragma unroll
            for (int ni = 0; ni < 2; ni++)
#pragma unroll
                for (int q = 0; q < 4; q++) acc[mi][ni][q] = 0.0f;

#define MMA_KS(mi, ks) do {                                                        \
        uint32_t kc = (uint32_t)(kcb + (ks) * 2 + klane);                          \
        uint32_t aaddr = hbs + (uint32_t)((((mi) * 16) + brow) * 2048)             \
                       + ((kc ^ asw) << 4);                                        \
        uint32_t ah0, ah1, ah2, ah3, al0, al1, al2, al3;                           \
        ldsm_x4(ah0, ah1, ah2, ah3, aaddr);                                        \
        ldsm_x4(al0, al1, al2, al3, aaddr + 65536u);                               \
        uint32_t kk = (uint32_t)(kbase + (ks) * 16 + brow);                        \
        uint32_t baddr = whb + kk * 32 + bswzB;                                    \
        uint32_t bh0, bh1, bh2, bh3, bl0, bl1, bl2, bl3;                           \
        ldsm_x4_t(bh0, bh1, bh2, bh3, baddr);                                      \
        ldsm_x4_t(bl0, bl1, bl2, bl3, baddr + 32768u);                             \
        mma16816(acc[mi][0], ah0, ah1, ah2, ah3, bh0, bh1);                        \
        mma16816(acc[mi][0], al0, al1, al2, al3, bh0, bh1);                        \
        mma16816(acc[mi][0], ah0, ah1, ah2, ah3, bl0, bl1);                        \
        mma16816(acc[mi][1], ah0, ah1, ah2, ah3, bh2, bh3);                        \
        mma16816(acc[mi][1], al0, al1, al2, al3, bh2, bh3);                        \
        mma16816(acc[mi][1], ah0, ah1, ah2, ah3, bl2, bl3);                        \
    } while (0)

        // m-tile 0 (b 0-15): gated on first two copy groups
        CP_WAIT(2); __syncwarp();
        MMA_KS(0, 0); MMA_KS(0, 1); MMA_KS(0, 2); MMA_KS(0, 3);
        MMA_KS(0, 4); MMA_KS(0, 5); MMA_KS(0, 6); MMA_KS(0, 7);
        // m-tile 1 (b 16-31)
        CP_WAIT(0); __syncwarp();
        MMA_KS(1, 0); MMA_KS(1, 1); MMA_KS(1, 2); MMA_KS(1, 3);
        MMA_KS(1, 4); MMA_KS(1, 5); MMA_KS(1, 6); MMA_KS(1, 7);
#undef MMA_KS

        // ---- stash partials p[w][b][c] ----
        const int rr  = lane >> 2;
        const int cc2 = (lane & 3) * 2;
#pragma unroll
        for (int mi = 0; mi < 2; mi++)
#pragma unroll
            for (int ni = 0; ni < 2; ni++) {
                float* pp = p_s + w * 512 + (mi * 16 + rr) * 16 + ni * 8 + cc2;
                *(float2*)pp         = make_float2(acc[mi][ni][0], acc[mi][ni][1]);
                *(float2*)(pp + 128) = make_float2(acc[mi][ni][2], acc[mi][ni][3]);
            }
        __syncthreads();

        // ---- reduce 8 k-partials, tanh, write ----
        float s0 = 0.0f, s1 = 0.0f;
        const float* pr = p_s + ob * 16 + ocl;
#pragma unroll
        for (int j = 0; j < 8; j++) {
            float2 v = *(const float2*)(pr + j * 512);
            s0 += v.x; s1 += v.y;
        }
        const float hn0 = tanh_acc(xv.x + s0);
        const float hn1 = tanh_acc(xv.y + s1);
        *(float2*)(xp + xidx) = make_float2(hn0, hn1);

        __nv_bfloat16 h0h = __float2bfloat16(hn0), h1h = __float2bfloat16(hn1);
        __nv_bfloat162 hh2; hh2.x = h0h; hh2.y = h1h;
        __nv_bfloat162 hl2;
        hl2.x = __float2bfloat16(hn0 - __bfloat162float(h0h));
        hl2.y = __float2bfloat16(hn1 - __bfloat162float(h1h));
        *(__nv_bfloat162*)(hhn + (size_t)ob * HH + oc) = hh2;
        *(__nv_bfloat162*)(hln + (size_t)ob * HH + oc) = hl2;

        grid_bar_sync(bar * NCTA_R); bar++;

        const __nv_bfloat16* th = hhc; hhc = hhn; hhn = (__nv_bfloat16*)th;
        const __nv_bfloat16* tl = hlc; hlc = hln; hln = (__nv_bfloat16*)tl;
    }
}

// -------------------- Final dense head --------------------
__global__ void __launch_bounds__(256)
fc_kernel(const float* __restrict__ seq, const float* __restrict__ fcW,
          const float* __restrict__ fcb, float* __restrict__ out)
{
    const int o  = blockIdx.x * 256 + threadIdx.x;
    const int bq = blockIdx.y;
    const float* h = seq + (size_t)((TT - 1) * BB + bq) * HH;
    float acc = fcb[o];
#pragma unroll 8
    for (int k = 0; k < HH; k++)
        acc = fmaf(h[k], fcW[k * HH + o], acc);
    out[bq * HH + o] = acc;
}

// -------------------- launch --------------------
extern "C" void kernel_launch(void* const* d_in, const int* in_sizes, int n_in,
                              void* d_out, int out_size)
{
    const float* x   = (const float*)d_in[0];
    const float* Wi  = (const float*)d_in[1];
    const float* Wh  = (const float*)d_in[2];
    const float* bl  = (const float*)d_in[3];
    const float* fcW = (const float*)d_in[4];
    const float* fcb = (const float*)d_in[5];
    float* out = (float*)d_out;

    cudaFuncSetAttribute(rnn_layer_mma_kernel,
                         cudaFuncAttributeMaxDynamicSharedMemorySize, RNN_SMEM_B);

    float* S;
    __nv_bfloat16 *Ah, *Al, *Wih, *Wil, *Whh, *Whl;
    cudaGetSymbolAddress((void**)&S,   g_S);
    cudaGetSymbolAddress((void**)&Ah,  g_Ah);
    cudaGetSymbolAddress((void**)&Al,  g_Al);
    cudaGetSymbolAddress((void**)&Wih, g_Wih);
    cudaGetSymbolAddress((void**)&Wil, g_Wil);
    cudaGetSymbolAddress((void**)&Whh, g_Whh);
    cudaGetSymbolAddress((void**)&Whl, g_Whl);

    const dim3 ggrid(8, 256);
    const int NSEQ4 = BB * TT * HH / 4;
    const int NW4   = LL * HH * HH / 4;

    split_tr_kernel<<<BB * TT, 256>>>(x, Ah, Al);
    split_kernel<<<2048, 256>>>(Wi, Wih, Wil, NW4);
    split_kernel<<<2048, 256>>>(Wh, Whh, Whl, NW4);

    for (int l = 0; l < LL; l++) {
        mma_gemm_kernel<<<ggrid, 256>>>(Ah, Al,
                                        Wih + (size_t)l * HH * HH,
                                        Wil + (size_t)l * HH * HH,
                                        bl + l * HH, S);
        rnn_layer_mma_kernel<<<NCTA_R, 256, RNN_SMEM_B>>>(S,
                                        Whh + (size_t)l * HH * HH,
                                        Whl + (size_t)l * HH * HH);
        if (l < LL - 1)
            split_kernel<<<4096, 256>>>(S, Ah, Al, NSEQ4);
    }

    fc_kernel<<<dim3(HH / 256, BB), 256>>>(S, fcW, fcb, out);
}